// round 3
// baseline (speedup 1.0000x reference)
#include <cuda_runtime.h>
#include <math.h>

#define Bn 2
#define Nn 512
#define Dn 64
#define EPSf 1e-8f

#define EST_OFF  ((size_t)0)
#define OUT_OFF  ((size_t)131072)
#define QIJ_OFF  ((size_t)262144)
#define Z_OFF    ((size_t)1310720)
#define LH_OFF   ((size_t)68419584)

// ---- device scratch ----
__device__ __align__(16) float g_t[Nn];
__device__ __align__(16) float g_efr[Nn*Dn];
__device__ __align__(16) float g_efi[Nn*Dn];
__device__ __align__(16) float g_Uq[Bn*Nn*128];      // [row][e]  e<64 real, e>=64 imag
__device__ __align__(16) float g_UkT[Bn*128*Nn];     // [b][e][j]
__device__ __align__(16) float g_Uv[Bn*Nn*128];      // [row][e]
__device__ __align__(16) float g_V [Bn*Nn*128];      // [row][e]
__device__ __align__(16) float g_e [Bn*Nn*128];      // er | ei combined
__device__ float g_nq[Bn*Nn];
__device__ float g_nk[Bn*Nn];

// ============================================================
// K0: t, e^{i phi} tables, lambda_h output
// ============================================================
__global__ void k_setup(const float* __restrict__ tm,
                        const float* __restrict__ lv,
                        float* __restrict__ out_lh)
{
    int idx = blockIdx.x * blockDim.x + threadIdx.x;   // 0..32767
    int i = idx >> 6;
    int d = idx & 63;
    float denom = tm[Nn - 1] - tm[0];
    float ti = tm[i] / denom;
    float lam = (d < 32) ? lv[d] : -lv[d - 32];
    float sph, cph;
    sincosf(ti * lam, &sph, &cph);
    g_efr[idx] = cph;
    g_efi[idx] = sph;
    if (d == 0) g_t[i] = ti;
    if (idx < 128) {
        float v;
        if (idx < 64) v = 0.f;
        else {
            int k = idx - 64;
            v = (k < 32) ? lv[k] : -lv[k - 32];
        }
        out_lh[idx] = v;
    }
}

// ============================================================
// K1: complex projections + twist. mode: 2 = V only, 0 = Q/K (y sel)
// grid (64, nm) ; block 256 ; 16 rows per block
// ============================================================
__global__ void __launch_bounds__(256) k_proj(
    const float* __restrict__ Zq, const float* __restrict__ Zk,
    const float* __restrict__ Zv,
    const float* __restrict__ Wq, const float* __restrict__ bq,
    const float* __restrict__ Wk, const float* __restrict__ bk,
    const float* __restrict__ Wv, const float* __restrict__ bv,
    int mode)
{
    int m   = (mode == 2) ? 2 : blockIdx.y;   // 0=q 1=k 2=v
    int tid = threadIdx.x;
    int d   = tid & 63;
    int sub = tid >> 6;

    const float* Z  = (m == 0) ? Zq : (m == 1) ? Zk : Zv;
    const float* W  = (m == 0) ? Wq : (m == 1) ? Wk : Wv;
    const float* bb = (m == 0) ? bq : (m == 1) ? bk : bv;

    __shared__ float sW0[64 * 65];
    __shared__ float sW1[64 * 65];
    __shared__ float zbuf[4][2][64];
    __shared__ float part[8];

    for (int idx = tid; idx < 4096; idx += 256) {
        int r = idx >> 6, c = idx & 63;
        sW0[r * 65 + c] = W[idx];
        sW1[r * 65 + c] = W[4096 + idx];
    }
    float bR = bb[d], bI = bb[64 + d];
    __syncthreads();

    for (int it = 0; it < 4; it++) {
        int row = blockIdx.x * 16 + it * 4 + sub;    // 0..1023
        int b = row >> 9, i = row & 511;

        zbuf[sub][0][d] = Z[((size_t)(b * 2 + 0) * Nn + i) * Dn + d];
        zbuf[sub][1][d] = Z[((size_t)(b * 2 + 1) * Nn + i) * Dn + d];
        __syncthreads();

        float yr = bR, yi = bI;
#pragma unroll 16
        for (int e = 0; e < 64; e++) {
            float w0 = sW0[d * 65 + e];
            float w1 = sW1[d * 65 + e];
            float a = zbuf[sub][0][e];
            float c = zbuf[sub][1][e];
            yr += a * w0 - c * w1;
            yi += a * w1 + c * w0;
        }

        float efr = g_efr[i * 64 + d];
        float efi = g_efi[i * 64 + d];
        float ur = efr * yr + efi * yi;     // U = conj(ef) * y
        float ui = efr * yi - efi * yr;

        if (m == 0)      { g_Uq[row * 128 + d] = ur; g_Uq[row * 128 + 64 + d] = ui; }
        else if (m == 1) { g_UkT[b * 65536 + d * 512 + i]        = ur;
                           g_UkT[b * 65536 + (64 + d) * 512 + i] = ui; }
        else             { g_Uv[row * 128 + d] = ur; g_Uv[row * 128 + 64 + d] = ui;
                           g_V [row * 128 + d] = yr; g_V [row * 128 + 64 + d] = yi; }

        if (m < 2) {
            float v = ur * ur + ui * ui;
#pragma unroll
            for (int off = 16; off > 0; off >>= 1)
                v += __shfl_down_sync(0xffffffffu, v, off);
            if ((tid & 31) == 0) part[tid >> 5] = v;
        }
        __syncthreads();
        if (m < 2 && d == 0) {
            float tot = part[sub * 2] + part[sub * 2 + 1];
            if (m == 0) g_nq[row] = tot;
            else        g_nk[row] = tot;
        }
    }
}

// ============================================================
// K2: tiled fused attention. 16 i-rows/block, 128-wide j tiles.
// grid 64 (b*32 + ib) ; block 256 ; ~108KB dynamic smem
// ============================================================
#define BI 16
#define TJ 128
__global__ void __launch_bounds__(256) k_attn(
    const float* __restrict__ losq, const float* __restrict__ lgsq,
    const float* __restrict__ nfp,  const float* __restrict__ taup,
    float* __restrict__ out)
{
    extern __shared__ float dyn[];
    float* kv  = dyn;                 // 128 e x 128 j  (reused as V tile: 128 j x 128 e)
    float* sQ  = kv + 16384;          // 16 i x 128 e
    float* s   = sQ + 2048;           // 16 i x 512 j
    float* st  = s  + 8192;           // t[512]
    float* snk = st + 512;            // nk[512]

    int tid  = threadIdx.x;
    int b    = blockIdx.x >> 5;
    int ib   = blockIdx.x & 31;
    int i0   = ib * BI;
    int w    = tid >> 5;
    int lane = tid & 31;

    // stage Q rows, t, nk ; init s = -inf
    {
        const float4* q4 = (const float4*)(g_Uq + (size_t)(b * 512 + i0) * 128);
        float4* sQ4 = (float4*)sQ;
        for (int k = tid; k < 512; k += 256) sQ4[k] = q4[k];
        for (int k = tid; k < 512; k += 256) { st[k] = g_t[k]; snk[k] = g_nk[b * 512 + k]; }
        for (int k = tid; k < 8192; k += 256) s[k] = -INFINITY;
    }

    float lo   = losq[0] * losq[0];
    float lg   = lgsq[0] * lgsq[0] + EPSf;
    float nf2  = nfp[0] * nfp[0] + EPSf;
    float tau2 = taup[0] * taup[0];

    int r0 = w * 2, r1 = w * 2 + 1;           // local rows of this warp
    int ig0 = i0 + r0, ig1 = i0 + r1;
    int jt_max = (i0 + BI - 1) >> 7;          // inclusive tile index

    __syncthreads();
    float ti0 = st[ig0], ti1 = st[ig1];
    float nq0 = g_nq[b * 512 + ig0], nq1 = g_nq[b * 512 + ig1];

    // ---------- scores ----------
    for (int jt = 0; jt <= jt_max; jt++) {
        int j0 = jt * TJ;
        __syncthreads();
        // stage K tile [e][j0..j0+127]
        {
            const float* src = g_UkT + b * 65536 + j0;
            float4* kv4 = (float4*)kv;
            for (int idx = tid; idx < 128 * 32; idx += 256) {
                int e = idx >> 5, jq = idx & 5 * 0 + (idx & 31);
                kv4[e * 32 + jq] = ((const float4*)(src + e * 512))[jq];
            }
        }
        __syncthreads();

        float4 a0 = {0,0,0,0}, a1 = {0,0,0,0};
        const float4* kv4 = (const float4*)kv;
#pragma unroll 8
        for (int e = 0; e < 128; e++) {
            float4 k4 = kv4[e * 32 + lane];
            float q0 = sQ[r0 * 128 + e];
            float q1 = sQ[r1 * 128 + e];
            a0.x += q0 * k4.x; a0.y += q0 * k4.y; a0.z += q0 * k4.z; a0.w += q0 * k4.w;
            a1.x += q1 * k4.x; a1.y += q1 * k4.y; a1.z += q1 * k4.z; a1.w += q1 * k4.w;
        }

        int j = j0 + lane * 4;
        float tj0 = st[j], tj1 = st[j+1], tj2 = st[j+2], tj3 = st[j+3];
        float nk0 = snk[j], nk1 = snk[j+1], nk2 = snk[j+2], nk3 = snk[j+3];

        float4 s0, s1;
        s0.x = (j   <= ig0) ? -tau2 * logf(nf2*(lo*fabsf(ti0-tj0)+lg) + nq0 + nk0 - 2.f*a0.x) : -INFINITY;
        s0.y = (j+1 <= ig0) ? -tau2 * logf(nf2*(lo*fabsf(ti0-tj1)+lg) + nq0 + nk1 - 2.f*a0.y) : -INFINITY;
        s0.z = (j+2 <= ig0) ? -tau2 * logf(nf2*(lo*fabsf(ti0-tj2)+lg) + nq0 + nk2 - 2.f*a0.z) : -INFINITY;
        s0.w = (j+3 <= ig0) ? -tau2 * logf(nf2*(lo*fabsf(ti0-tj3)+lg) + nq0 + nk3 - 2.f*a0.w) : -INFINITY;
        s1.x = (j   <= ig1) ? -tau2 * logf(nf2*(lo*fabsf(ti1-tj0)+lg) + nq1 + nk0 - 2.f*a1.x) : -INFINITY;
        s1.y = (j+1 <= ig1) ? -tau2 * logf(nf2*(lo*fabsf(ti1-tj1)+lg) + nq1 + nk1 - 2.f*a1.y) : -INFINITY;
        s1.z = (j+2 <= ig1) ? -tau2 * logf(nf2*(lo*fabsf(ti1-tj2)+lg) + nq1 + nk2 - 2.f*a1.z) : -INFINITY;
        s1.w = (j+3 <= ig1) ? -tau2 * logf(nf2*(lo*fabsf(ti1-tj3)+lg) + nq1 + nk3 - 2.f*a1.w) : -INFINITY;

        ((float4*)(s + r0 * 512))[j0/4 + lane] = s0;
        ((float4*)(s + r1 * 512))[j0/4 + lane] = s1;
    }
    __syncthreads();

    // ---------- softmax + write A ----------
    for (int rep = 0; rep < 2; rep++) {
        int r = w * 2 + rep;
        int ig = i0 + r;
        float* srow = s + r * 512;
        float mx = -INFINITY;
        for (int k = lane; k < 512; k += 32) mx = fmaxf(mx, srow[k]);
#pragma unroll
        for (int off = 16; off > 0; off >>= 1)
            mx = fmaxf(mx, __shfl_xor_sync(0xffffffffu, mx, off));
        float sum = 0.f;
        for (int k = lane; k < 512; k += 32) {
            float e = expf(srow[k] - mx);
            srow[k] = e;
            sum += e;
        }
#pragma unroll
        for (int off = 16; off > 0; off >>= 1)
            sum += __shfl_xor_sync(0xffffffffu, sum, off);
        float inv = 1.f / sum;
        size_t qoffr = QIJ_OFF + ((size_t)(b * 2 + 0) * 512 + ig) * 512;
        size_t qoffi = QIJ_OFF + ((size_t)(b * 2 + 1) * 512 + ig) * 512;
        for (int k = lane; k < 512; k += 32) {
            float a = srow[k] * inv;
            srow[k] = a;
            out[qoffr + k] = a;
            out[qoffi + k] = 0.f;
        }
    }
    __syncthreads();

    // ---------- AV: e[i][:] = sum_j A[i][j] * Uv[j][:] ----------
    float4 c0 = {0,0,0,0}, c1 = {0,0,0,0};
    for (int jt = 0; jt <= jt_max; jt++) {
        int j0 = jt * TJ;
        __syncthreads();
        {
            const float4* src = (const float4*)(g_Uv + (size_t)(b * 512 + j0) * 128);
            float4* kv4 = (float4*)kv;
            for (int k = tid; k < 128 * 32; k += 256) kv4[k] = src[k];
        }
        __syncthreads();
        const float4* v4 = (const float4*)kv;
#pragma unroll 8
        for (int jj = 0; jj < TJ; jj++) {
            float a0 = s[r0 * 512 + j0 + jj];
            float a1 = s[r1 * 512 + j0 + jj];
            float4 vv = v4[jj * 32 + lane];
            c0.x += a0 * vv.x; c0.y += a0 * vv.y; c0.z += a0 * vv.z; c0.w += a0 * vv.w;
            c1.x += a1 * vv.x; c1.y += a1 * vv.y; c1.z += a1 * vv.z; c1.w += a1 * vv.w;
        }
    }
    ((float4*)(g_e + (size_t)(b * 512 + ig0) * 128))[lane] = c0;
    ((float4*)(g_e + (size_t)(b * 512 + ig1) * 128))[lane] = c1;
}

// ============================================================
// K3: estv / est_latent / P / output projection
// grid 64 ; block 256 ; 16 rows per block
// ============================================================
__global__ void __launch_bounds__(256) k_epi(
    const float* __restrict__ Wp, const float* __restrict__ bp,
    const float* __restrict__ etap, float* __restrict__ out)
{
    int tid = threadIdx.x;
    int d   = tid & 63;
    int sub = tid >> 6;

    __shared__ float sW0[64 * 65];
    __shared__ float sW1[64 * 65];
    __shared__ float pbuf[4][2][64];

    for (int idx = tid; idx < 4096; idx += 256) {
        int r = idx >> 6, c = idx & 63;
        sW0[r * 65 + c] = Wp[idx];
        sW1[r * 65 + c] = Wp[4096 + idx];
    }
    float bR = bp[d], bI = bp[64 + d];
    float eta = 1.f / (1.f + expf(-etap[d]));
    float g   = 1.f / (1.f + expf(-eta));
    __syncthreads();

    for (int it = 0; it < 4; it++) {
        int row = blockIdx.x * 16 + it * 4 + sub;
        int b = row >> 9, i = row & 511;

        float efr = g_efr[i * 64 + d];
        float efi = g_efi[i * 64 + d];
        float er = g_e[row * 128 + d];
        float ei = g_e[row * 128 + 64 + d];
        float estr = efr * er - efi * ei;
        float esti = efr * ei + efi * er;

        float elr = (1.f - eta) * g_V[row * 128 + d]      + g * estr;
        float eli = (1.f - eta) * g_V[row * 128 + 64 + d] + g * esti;

        out[EST_OFF + ((size_t)(b * 2 + 0) * 512 + i) * 64 + d] = elr;
        out[EST_OFF + ((size_t)(b * 2 + 1) * 512 + i) * 64 + d] = eli;

        pbuf[sub][0][d] = efr * elr - efi * eli;
        pbuf[sub][1][d] = efr * eli + efi * elr;
        __syncthreads();

        float yr = bR, yi = bI;
#pragma unroll 16
        for (int e = 0; e < 64; e++) {
            float w0 = sW0[d * 65 + e];
            float w1 = sW1[d * 65 + e];
            float a = pbuf[sub][0][e];
            float c = pbuf[sub][1][e];
            yr += a * w0 - c * w1;
            yi += a * w1 + c * w0;
        }
        out[OUT_OFF + ((size_t)(b * 2 + 0) * 512 + i) * 64 + d] = yr;
        out[OUT_OFF + ((size_t)(b * 2 + 1) * 512 + i) * 64 + d] = yi;
        __syncthreads();
    }
}

// ============================================================
// K4: Z_ij_hat_all — 268 MB streaming write.
// grid (B*N) ; block 256
// ============================================================
__global__ void __launch_bounds__(256) k_zij(float* __restrict__ out)
{
    int row = blockIdx.x;
    int b = row >> 9, i = row & 511;
    int tid = threadIdx.x;

    __shared__ __align__(16) float efr[64], efi[64];
    if (tid < 64)            efr[tid]      = g_efr[i * 64 + tid];
    else if (tid < 128)      efi[tid - 64] = g_efi[i * 64 + (tid - 64)];
    __syncthreads();

    const float4* uv4 = (const float4*)(g_Uv + (size_t)b * 512 * 128);
    float4* zr4 = (float4*)(out + Z_OFF + ((size_t)(b * 2 + 0) * 512 + i) * 512 * 64);
    float4* zi4 = (float4*)(out + Z_OFF + ((size_t)(b * 2 + 1) * 512 + i) * 512 * 64);

    for (int k = tid; k < 512 * 16; k += 256) {
        int j  = k >> 4;
        int d4 = k & 15;
        int d  = d4 << 2;
        float4 vr = uv4[j * 32 + d4];
        float4 vi = uv4[j * 32 + 16 + d4];
        float e0 = efr[d],     f0 = efi[d];
        float e1 = efr[d + 1], f1 = efi[d + 1];
        float e2 = efr[d + 2], f2 = efi[d + 2];
        float e3 = efr[d + 3], f3 = efi[d + 3];
        float4 zr, zi;
        zr.x = e0 * vr.x - f0 * vi.x;  zi.x = e0 * vi.x + f0 * vr.x;
        zr.y = e1 * vr.y - f1 * vi.y;  zi.y = e1 * vi.y + f1 * vr.y;
        zr.z = e2 * vr.z - f2 * vi.z;  zi.z = e2 * vi.z + f2 * vr.z;
        zr.w = e3 * vr.w - f3 * vi.w;  zi.w = e3 * vi.w + f3 * vr.w;
        __stcs(&zr4[k], zr);
        __stcs(&zi4[k], zi);
    }
}

// ============================================================
extern "C" void kernel_launch(void* const* d_in, const int* in_sizes, int n_in,
                              void* d_out, int out_size)
{
    const float* Zq   = (const float*)d_in[0];
    const float* Zk   = (const float*)d_in[1];
    const float* Zv   = (const float*)d_in[2];
    const float* tm   = (const float*)d_in[3];
    const float* Wq   = (const float*)d_in[4];
    const float* bq   = (const float*)d_in[5];
    const float* Wk   = (const float*)d_in[6];
    const float* bk   = (const float*)d_in[7];
    const float* Wv   = (const float*)d_in[8];
    const float* bv   = (const float*)d_in[9];
    const float* Wp   = (const float*)d_in[10];
    const float* bp   = (const float*)d_in[11];
    const float* lv   = (const float*)d_in[12];
    const float* losq = (const float*)d_in[13];
    const float* lgsq = (const float*)d_in[14];
    const float* nf   = (const float*)d_in[15];
    const float* tau  = (const float*)d_in[16];
    const float* etap = (const float*)d_in[17];
    float* out = (float*)d_out;

    static cudaStream_t s_z = nullptr;
    static cudaEvent_t ev_fork = nullptr, ev_join = nullptr;
    static int attn_smem = (16384 + 2048 + 8192 + 512 + 512) * 4;
    if (s_z == nullptr) {
        cudaStreamCreateWithFlags(&s_z, cudaStreamNonBlocking);
        cudaEventCreateWithFlags(&ev_fork, cudaEventDisableTiming);
        cudaEventCreateWithFlags(&ev_join, cudaEventDisableTiming);
        cudaFuncSetAttribute(k_attn, cudaFuncAttributeMaxDynamicSharedMemorySize, attn_smem);
    }

    k_setup<<<64, 512>>>(tm, lv, out + LH_OFF);
    // V projection first so the Z-plane writer can fork early
    k_proj<<<dim3(64, 1), 256>>>(Zq, Zk, Zv, Wq, bq, Wk, bk, Wv, bv, 2);

    cudaEventRecord(ev_fork, 0);
    cudaStreamWaitEvent(s_z, ev_fork, 0);
    k_zij<<<Bn * Nn, 256, 0, s_z>>>(out);
    cudaEventRecord(ev_join, s_z);

    k_proj<<<dim3(64, 2), 256>>>(Zq, Zk, Zv, Wq, bq, Wk, bk, Wv, bv, 0);
    k_attn<<<64, 256, attn_smem>>>(losq, lgsq, nf, tau, out);
    k_epi<<<64, 256>>>(Wp, bp, etap, out);

    cudaStreamWaitEvent(0, ev_join, 0);
}